// round 1
// baseline (speedup 1.0000x reference)
#include <cuda_runtime.h>
#include <cuda_bf16.h>

// Problem constants (from reference setup_inputs)
#define V_SZ 8
#define J_SZ 64
#define NTHREADS 256
// 400^0.9 computed in double precision: exp(0.9*ln(400)) = 219.7119...
#define T09 219.711923f
#define THRESH 400.0f

// Scratch accumulator (allocation-free rule: __device__ global)
__device__ double g_accum;

__global__ void pl_zero_kernel() { g_accum = 0.0; }

__global__ void __launch_bounds__(NTHREADS) pl_loss_kernel(
    const float* __restrict__ kgt,   // [B,J,3]
    const float* __restrict__ kpr,   // [B,J,3]
    const float* __restrict__ gR,    // [B,V,3,3]
    const float* __restrict__ gt,    // [B,V,3]
    const float* __restrict__ Km,    // [V,3,3]
    const float* __restrict__ cam)   // [B,V,3,4]
{
    __shared__ float s_gt[J_SZ * 3];
    __shared__ float s_pr[J_SZ * 3];
    __shared__ float s_R[V_SZ * 9];
    __shared__ float s_t[V_SZ * 3];
    __shared__ float s_cam[V_SZ * 12];
    __shared__ float s_K[V_SZ * 9];
    __shared__ float s_warp[NTHREADS / 32];

    const int b   = blockIdx.x;
    const int tid = threadIdx.x;

    // Stage per-batch data (coalesced)
    const float* gt_b = kgt + (size_t)b * J_SZ * 3;
    const float* pr_b = kpr + (size_t)b * J_SZ * 3;
    #pragma unroll
    for (int i = tid; i < J_SZ * 3; i += NTHREADS) {
        s_gt[i] = gt_b[i];
        s_pr[i] = pr_b[i];
    }
    if (tid < V_SZ * 9)  s_R[tid]   = gR[(size_t)b * V_SZ * 9 + tid];
    if (tid < V_SZ * 3)  s_t[tid]   = gt[(size_t)b * V_SZ * 3 + tid];
    if (tid < V_SZ * 12) s_cam[tid] = cam[(size_t)b * V_SZ * 12 + tid];
    if (tid < V_SZ * 9)  s_K[tid]   = Km[tid];
    __syncthreads();

    float acc = 0.0f;
    #pragma unroll
    for (int p = tid; p < V_SZ * J_SZ; p += NTHREADS) {
        const int v = p >> 6;       // p / 64
        const int j = p & 63;       // p % 64
        const float* Rv = s_R   + v * 9;
        const float* tv = s_t   + v * 3;
        const float* Cv = s_cam + v * 12;
        const float* Kv = s_K   + v * 9;

        // ---- GT projection: x = K (R X + t), perspective divide
        const float X0 = s_gt[j * 3 + 0];
        const float X1 = s_gt[j * 3 + 1];
        const float X2 = s_gt[j * 3 + 2];
        const float Xc0 = Rv[0] * X0 + Rv[1] * X1 + Rv[2] * X2 + tv[0];
        const float Xc1 = Rv[3] * X0 + Rv[4] * X1 + Rv[5] * X2 + tv[1];
        const float Xc2 = Rv[6] * X0 + Rv[7] * X1 + Rv[8] * X2 + tv[2];
        const float x0 = Kv[0] * Xc0 + Kv[1] * Xc1 + Kv[2] * Xc2;
        const float x1 = Kv[3] * Xc0 + Kv[4] * Xc1 + Kv[5] * Xc2;
        const float x2 = Kv[6] * Xc0 + Kv[7] * Xc1 + Kv[8] * Xc2;
        const float gx = x0 / x2;
        const float gy = x1 / x2;

        // ---- Predicted projection: xp = K (cam [X;1]), perspective divide
        const float P0 = s_pr[j * 3 + 0];
        const float P1 = s_pr[j * 3 + 1];
        const float P2 = s_pr[j * 3 + 2];
        const float Y0 = Cv[0] * P0 + Cv[1] * P1 + Cv[2]  * P2 + Cv[3];
        const float Y1 = Cv[4] * P0 + Cv[5] * P1 + Cv[6]  * P2 + Cv[7];
        const float Y2 = Cv[8] * P0 + Cv[9] * P1 + Cv[10] * P2 + Cv[11];
        const float y0 = Kv[0] * Y0 + Kv[1] * Y1 + Kv[2] * Y2;
        const float y1 = Kv[3] * Y0 + Kv[4] * Y1 + Kv[5] * Y2;
        const float y2 = Kv[6] * Y0 + Kv[7] * Y1 + Kv[8] * Y2;
        const float px = y0 / y2;
        const float py = y1 / y2;

        // ---- Smooth MSE
        float dx = gx - px; dx = dx * dx;
        float dy = gy - py; dy = dy * dy;
        acc += (dx > THRESH) ? (powf(dx, 0.1f) * T09) : dx;
        acc += (dy > THRESH) ? (powf(dy, 0.1f) * T09) : dy;
    }

    // ---- Block reduction
    #pragma unroll
    for (int o = 16; o > 0; o >>= 1)
        acc += __shfl_down_sync(0xFFFFFFFFu, acc, o);
    if ((tid & 31) == 0) s_warp[tid >> 5] = acc;
    __syncthreads();
    if (tid < (NTHREADS / 32)) {
        float s = s_warp[tid];
        #pragma unroll
        for (int o = (NTHREADS / 64); o > 0; o >>= 1)
            s += __shfl_down_sync(0xFFu, s, o);
        if (tid == 0) atomicAdd(&g_accum, (double)s);
    }
}

__global__ void pl_finalize_kernel(float* out, int B) {
    // per-batch sum / dim(=2), then mean over B
    *out = (float)(g_accum / (2.0 * (double)B));
}

extern "C" void kernel_launch(void* const* d_in, const int* in_sizes, int n_in,
                              void* d_out, int out_size) {
    const float* kgt = (const float*)d_in[0];   // [B,J,3]
    const float* kpr = (const float*)d_in[1];   // [B,J,3]
    const float* gR  = (const float*)d_in[2];   // [B,V,3,3]
    const float* gt  = (const float*)d_in[3];   // [B,V,3]
    const float* Km  = (const float*)d_in[4];   // [V,3,3]
    const float* cam = (const float*)d_in[5];   // [B,V,3,4]
    float* out = (float*)d_out;

    const int B = in_sizes[0] / (J_SZ * 3);

    pl_zero_kernel<<<1, 1>>>();
    pl_loss_kernel<<<B, NTHREADS>>>(kgt, kpr, gR, gt, Km, cam);
    pl_finalize_kernel<<<1, 1>>>(out, B);
}

// round 2
// speedup vs baseline: 1.5270x; 1.5270x over previous
#include <cuda_runtime.h>
#include <cuda_bf16.h>

// Problem constants (from reference setup_inputs)
#define V_SZ 8
#define J_SZ 64
#define NTHREADS 256          // 8 warps == V_SZ views
#define BPB 8                 // batches per block
#define T09 219.711923f       // 400^0.9
#define THRESH 400.0f
#define MAX_BLOCKS 4096

// Scratch (allocation-free rule: __device__ globals)
__device__ float g_part[MAX_BLOCKS];

__global__ void __launch_bounds__(NTHREADS) pl_loss_kernel(
    const float* __restrict__ kgt,   // [B,J,3]
    const float* __restrict__ kpr,   // [B,J,3]
    const float* __restrict__ gR,    // [B,V,3,3]
    const float* __restrict__ gt,    // [B,V,3]
    const float* __restrict__ Km,    // [V,3,3]
    const float* __restrict__ cam,   // [B,V,3,4]
    int B)
{
    // Raw staged data, 16B aligned regions:
    // [0,192)=gt, [192,384)=pr, [384,456)=R, [456,480)=t, [480,576)=cam
    __shared__ __align__(16) float sh[576];
    __shared__ float s_K[V_SZ * 9];
    __shared__ float s_M[V_SZ * 12];   // K @ [R|t]
    __shared__ float s_Mc[V_SZ * 12];  // K @ cam
    __shared__ float s_wsum[NTHREADS / 32];

    const int tid  = threadIdx.x;
    const int w    = tid >> 5;    // warp == view
    const int lane = tid & 31;

    // Stage K once (72 floats, same for all batches)
    if (tid < V_SZ * 9) s_K[tid] = Km[tid];

    float acc = 0.0f;

    for (int bb = 0; bb < BPB; bb++) {
        const int b = blockIdx.x * BPB + bb;
        if (b >= B) break;

        // ---- Stage per-batch data with float4 (all base offsets 16B aligned)
        float4* sh4 = reinterpret_cast<float4*>(sh);
        if (tid < 48) {
            sh4[tid] = reinterpret_cast<const float4*>(kgt + (size_t)b * 192)[tid];
        } else if (tid < 96) {
            sh4[tid] = reinterpret_cast<const float4*>(kpr + (size_t)b * 192)[tid - 48];
        } else if (tid < 114) {
            sh4[tid] = reinterpret_cast<const float4*>(gR + (size_t)b * 72)[tid - 96];
        } else if (tid < 120) {
            sh4[tid] = reinterpret_cast<const float4*>(gt + (size_t)b * 24)[tid - 114];
        } else if (tid < 144) {
            sh4[tid] = reinterpret_cast<const float4*>(cam + (size_t)b * 96)[tid - 120];
        }
        __syncthreads();

        // ---- Fuse intrinsics: M = K@[R|t], Mc = K@cam (192 entries, 3 FMA each)
        if (tid < 192) {
            const int v = tid / 24;
            const int r = tid % 24;
            const float* Kv = s_K + v * 9;
            if (r < 12) {
                const int i = r >> 2, c = r & 3;
                float e0, e1, e2;
                if (c < 3) {
                    const float* Rv = sh + 384 + v * 9;
                    e0 = Rv[0 * 3 + c]; e1 = Rv[1 * 3 + c]; e2 = Rv[2 * 3 + c];
                } else {
                    const float* tv = sh + 456 + v * 3;
                    e0 = tv[0]; e1 = tv[1]; e2 = tv[2];
                }
                s_M[v * 12 + r] = Kv[i * 3 + 0] * e0 + Kv[i * 3 + 1] * e1 + Kv[i * 3 + 2] * e2;
            } else {
                const int r2 = r - 12;
                const int i = r2 >> 2, c = r2 & 3;
                const float* Cv = sh + 480 + v * 12;
                s_Mc[v * 12 + r2] = Kv[i * 3 + 0] * Cv[0 * 4 + c]
                                  + Kv[i * 3 + 1] * Cv[1 * 4 + c]
                                  + Kv[i * 3 + 2] * Cv[2 * 4 + c];
            }
        }
        __syncthreads();

        // ---- Hoist this warp's view matrices into registers (broadcast LDS)
        float m[12], mc[12];
        #pragma unroll
        for (int i = 0; i < 12; i++) { m[i] = s_M[w * 12 + i]; mc[i] = s_Mc[w * 12 + i]; }

        #pragma unroll
        for (int jj = 0; jj < 2; jj++) {
            const int j = lane + jj * 32;
            // GT keypoint (stride-3: conflict-free, 3 coprime with 32 banks)
            const float X0 = sh[j * 3 + 0];
            const float X1 = sh[j * 3 + 1];
            const float X2 = sh[j * 3 + 2];
            const float x0 = m[0] * X0 + m[1] * X1 + m[2]  * X2 + m[3];
            const float x1 = m[4] * X0 + m[5] * X1 + m[6]  * X2 + m[7];
            const float x2 = m[8] * X0 + m[9] * X1 + m[10] * X2 + m[11];
            const float ig = __fdividef(1.0f, x2);
            const float gx = x0 * ig, gy = x1 * ig;

            // Predicted keypoint
            const float P0 = sh[192 + j * 3 + 0];
            const float P1 = sh[192 + j * 3 + 1];
            const float P2 = sh[192 + j * 3 + 2];
            const float y0 = mc[0] * P0 + mc[1] * P1 + mc[2]  * P2 + mc[3];
            const float y1 = mc[4] * P0 + mc[5] * P1 + mc[6]  * P2 + mc[7];
            const float y2 = mc[8] * P0 + mc[9] * P1 + mc[10] * P2 + mc[11];
            const float ip = __fdividef(1.0f, y2);
            const float px = y0 * ip, py = y1 * ip;

            float dx = gx - px; dx *= dx;
            float dy = gy - py; dy *= dy;
            acc += (dx > THRESH) ? (__powf(dx, 0.1f) * T09) : dx;
            acc += (dy > THRESH) ? (__powf(dy, 0.1f) * T09) : dy;
        }
        __syncthreads();   // staged data consumed; safe to overwrite next iter
    }

    // ---- Block reduction, one global write per block
    #pragma unroll
    for (int o = 16; o > 0; o >>= 1)
        acc += __shfl_down_sync(0xFFFFFFFFu, acc, o);
    if (lane == 0) s_wsum[w] = acc;
    __syncthreads();
    if (tid < (NTHREADS / 32)) {
        float s = s_wsum[tid];
        #pragma unroll
        for (int o = (NTHREADS / 64); o > 0; o >>= 1)
            s += __shfl_down_sync(0xFFu, s, o);
        if (tid == 0) g_part[blockIdx.x] = s;
    }
}

__global__ void __launch_bounds__(NTHREADS) pl_finalize_kernel(float* out, int nblocks, int B) {
    __shared__ double s_wsum[NTHREADS / 32];
    const int tid = threadIdx.x;
    double s = 0.0;
    for (int i = tid; i < nblocks; i += NTHREADS) s += (double)g_part[i];
    #pragma unroll
    for (int o = 16; o > 0; o >>= 1)
        s += __shfl_down_sync(0xFFFFFFFFu, s, o);
    if ((tid & 31) == 0) s_wsum[tid >> 5] = s;
    __syncthreads();
    if (tid < (NTHREADS / 32)) {
        double t = s_wsum[tid];
        #pragma unroll
        for (int o = (NTHREADS / 64); o > 0; o >>= 1)
            t += __shfl_down_sync(0xFFu, t, o);
        if (tid == 0) *out = (float)(t / (2.0 * (double)B));
    }
}

extern "C" void kernel_launch(void* const* d_in, const int* in_sizes, int n_in,
                              void* d_out, int out_size) {
    const float* kgt = (const float*)d_in[0];   // [B,J,3]
    const float* kpr = (const float*)d_in[1];   // [B,J,3]
    const float* gR  = (const float*)d_in[2];   // [B,V,3,3]
    const float* gt  = (const float*)d_in[3];   // [B,V,3]
    const float* Km  = (const float*)d_in[4];   // [V,3,3]
    const float* cam = (const float*)d_in[5];   // [B,V,3,4]
    float* out = (float*)d_out;

    const int B = in_sizes[0] / (J_SZ * 3);
    const int nblocks = (B + BPB - 1) / BPB;   // 2048 for B=16384

    pl_loss_kernel<<<nblocks, NTHREADS>>>(kgt, kpr, gR, gt, Km, cam, B);
    pl_finalize_kernel<<<1, NTHREADS>>>(out, nblocks, B);
}